// round 12
// baseline (speedup 1.0000x reference)
#include <cuda_runtime.h>
#include <cuda_fp16.h>
#include <math.h>
#include <stdint.h>

#define S_LEN  2048
#define BSZ    2
#define DMODEL 512
#define NHEADS 8
#define DHEAD  64
#define ZB     (BSZ*NHEADS)          // 16
#define MROWS  (S_LEN*BSZ)           // 4096
#define NWIN   32
#define KSX    512                   // X row: fp16 hi only
#define KSW    512                   // W row: fp16 hi only
#define NTOT   1536                  // Q,K,V columns stacked
#define KC     64                    // K chunk (fp16) = 128B rows
#define NCHUNK 8                     // uniform: single-pass fp16
#define STAGES 3
#define ATILE  16384                 // 128 x 64 fp16
#define BTILE  16384
#define STAGE_BYTES (ATILE+BTILE)
#define SMEM_BYTES  (STAGES*STAGE_BYTES)   // 96 KB
#define RCHUNK 16                    // s-chunks per z in reduce_kv

// Kernel-1 block roles
#define XCV_BLOCKS  512              // X convert: 4 float4 / thread
#define WCV_BLOCKS  768              // W convert: 1 float4 / thread
#define FIL_BLOCKS  512              // bias fill of ALL 2048 rows
#define QW_BLOCKS   16               // exact fp32 window-Q rows
#define K1_BLOCKS   (XCV_BLOCKS + WCV_BLOCKS + FIL_BLOCKS + QW_BLOCKS) // 1808

// ---------------- static scratch (no cudaMalloc allowed) -------------------
__device__ __align__(16) __half g_Xc[(size_t)MROWS*KSX];  // 4.2 MB
__device__ __align__(16) __half g_Wc[(size_t)NTOT*KSW];   // 1.6 MB
__device__ __align__(16) float g_Q[(size_t)ZB*S_LEN*DHEAD];
__device__ __align__(16) float g_K[(size_t)ZB*S_LEN*DHEAD];
__device__ __align__(16) float g_V[(size_t)ZB*S_LEN*DHEAD];
__device__ __align__(16) float g_Qw[BSZ*NWIN*DMODEL];     // exact window-q rows
__device__ __align__(16) float g_k2p[ZB*RCHUNK*DHEAD];
__device__ __align__(16) float g_v2p[ZB*RCHUNK*DHEAD];
__device__ __align__(16) float g_k2[ZB*DHEAD];
__device__ __align__(16) float g_v2[ZB*DHEAD];
__device__ int   g_cnt[ZB];          // replay-safe via &15
__device__ __align__(16) float g_c[ZB*NWIN];

// ---------------- helpers ---------------------------------------------------
__device__ __forceinline__ uint32_t smem_u32(const void* p) {
    uint32_t a;
    asm("{ .reg .u64 t; cvta.to.shared.u64 t, %1; cvt.u32.u64 %0, t; }"
        : "=r"(a) : "l"(p));
    return a;
}
__device__ __forceinline__ uint32_t swz(uint32_t off) {
    return off ^ ((off >> 3) & 0x70);      // SW128
}
__device__ __forceinline__ void cp16(uint32_t saddr, const void* g) {
    asm volatile("cp.async.cg.shared.global [%0], [%1], 16;"
                 :: "r"(saddr), "l"(g) : "memory");
}
#define CP_COMMIT() asm volatile("cp.async.commit_group;" ::: "memory")
#define CP_WAIT(n)  asm volatile("cp.async.wait_group %0;" :: "n"(n) : "memory")

__device__ __forceinline__ void ldmx4(uint32_t& r0, uint32_t& r1,
                                      uint32_t& r2, uint32_t& r3, uint32_t a) {
    asm volatile("ldmatrix.sync.aligned.m8n8.x4.shared.b16 {%0,%1,%2,%3}, [%4];"
                 : "=r"(r0), "=r"(r1), "=r"(r2), "=r"(r3) : "r"(a));
}
__device__ __forceinline__ void mma16816(float* c, const uint32_t* a,
                                         uint32_t b0, uint32_t b1) {
    asm volatile(
        "mma.sync.aligned.m16n8k16.row.col.f32.f16.f16.f32 "
        "{%0,%1,%2,%3}, {%4,%5,%6,%7}, {%8,%9}, {%0,%1,%2,%3};"
        : "+f"(c[0]), "+f"(c[1]), "+f"(c[2]), "+f"(c[3])
        : "r"(a[0]), "r"(a[1]), "r"(a[2]), "r"(a[3]), "r"(b0), "r"(b1));
}

// ---------------------------------------------------------------------------
// Kernel A:
//   [0,512)       : X -> fp16 (hi only), 4 float4/thread
//   [512,1280)    : W -> fp16 (hi only)
//   [1280,1792)   : bias fill of ALL 2048 output rows (atomic base)
//   [1792,1808)   : exact fp32 window-Q rows: g_Qw[b][w][n] = x[s_w,b]·Wq[n] + bq[n]
// ---------------------------------------------------------------------------
__global__ __launch_bounds__(256) void convert_xw(
    const float* __restrict__ x,
    const float* __restrict__ Wq, const float* __restrict__ bq,
    const float* __restrict__ Wk, const float* __restrict__ Wv,
    float* __restrict__ out, const float* __restrict__ bo)
{
    const int tid = threadIdx.x;
    const int bid = blockIdx.x;
    const int W4PM = DMODEL / 4;                       // 128 float4 per row

    if (bid < XCV_BLOCKS) {
        #pragma unroll
        for (int j = 0; j < 4; j++) {
            const int tid4 = bid * 1024 + j * 256 + tid;
            const float4 v = ((const float4*)x)[tid4];
            const int m    = tid4 / W4PM;
            const int koff = (tid4 % W4PM) * 4;
            __half2 hi01 = __halves2half2(__float2half_rn(v.x), __float2half_rn(v.y));
            __half2 hi23 = __halves2half2(__float2half_rn(v.z), __float2half_rn(v.w));
            __half2* d0 = (__half2*)(g_Xc + (size_t)m * KSX + koff);
            d0[0] = hi01; d0[1] = hi23;
        }
    } else if (bid < XCV_BLOCKS + WCV_BLOCKS) {
        const int wi   = (bid - XCV_BLOCKS) * 256 + tid;
        const int n    = wi / W4PM;
        const int koff = (wi % W4PM) * 4;
        const int sel  = n >> 9, row = n & 511;
        const float* W = (sel == 0) ? Wq : (sel == 1) ? Wk : Wv;
        const float4 v = *(const float4*)(W + (size_t)row * DMODEL + koff);
        __half2 hi01 = __halves2half2(__float2half_rn(v.x), __float2half_rn(v.y));
        __half2 hi23 = __halves2half2(__float2half_rn(v.z), __float2half_rn(v.w));
        __half2* d0 = (__half2*)(g_Wc + (size_t)n * KSW + koff);
        d0[0] = hi01; d0[1] = hi23;
    } else if (bid < XCV_BLOCKS + WCV_BLOCKS + FIL_BLOCKS) {
        __shared__ __align__(16) float4 sb[128];
        if (tid < 128) sb[tid] = ((const float4*)bo)[tid];
        __syncthreads();
        const int blk = bid - (XCV_BLOCKS + WCV_BLOCKS);   // 0..511
        float4* out4 = (float4*)out;
        #pragma unroll
        for (int j = 0; j < 4; j++) {
            const int idx = blk * 1024 + j * 256 + tid;
            out4[idx] = sb[idx & 127];
        }
    } else {
        // exact fp32 window-Q: block qb covers n = qb*32 .. +31 for all 64 rows
        const int qb = bid - (XCV_BLOCKS + WCV_BLOCKS + FIL_BLOCKS);  // 0..15
        const int n0 = qb * 32;
        const int r    = tid >> 2;          // 0..63 : (w, b) row index
        const int jsub = tid & 3;           // n sub-lane
        const int w_i  = r & 31;
        const int b_i  = r >> 5;
        const int s_pos = 64 * w_i + 63;

        const float4* __restrict__ xrow =
            (const float4*)(x + ((size_t)s_pos * BSZ + b_i) * DMODEL);
        const float4* __restrict__ wrows[8];
        #pragma unroll
        for (int j = 0; j < 8; j++)
            wrows[j] = (const float4*)(Wq + (size_t)(n0 + jsub + 4 * j) * DMODEL);

        float acc[8] = {};
        #pragma unroll 4
        for (int k4 = 0; k4 < DMODEL / 4; k4++) {
            const float4 xv = xrow[k4];
            #pragma unroll
            for (int j = 0; j < 8; j++) {
                const float4 wv = wrows[j][k4];
                acc[j] = fmaf(xv.x, wv.x, acc[j]);
                acc[j] = fmaf(xv.y, wv.y, acc[j]);
                acc[j] = fmaf(xv.z, wv.z, acc[j]);
                acc[j] = fmaf(xv.w, wv.w, acc[j]);
            }
        }
        float* dst = g_Qw + ((size_t)(b_i * NWIN + w_i)) * DMODEL;
        #pragma unroll
        for (int j = 0; j < 8; j++) {
            const int n = n0 + jsub + 4 * j;
            dst[n] = acc[j] + bq[n];
        }
    }
}

// ---------------------------------------------------------------------------
// Kernel B: fp16 warp-MMA GEMM, single pass (8 chunks) for Q, K, V.
// ---------------------------------------------------------------------------
__global__ __launch_bounds__(256, 2) void gemm_mma(
    const float* __restrict__ bq, const float* __restrict__ bk,
    const float* __restrict__ bv, const float* __restrict__ beta)
{
    extern __shared__ __align__(1024) char smem[];
    const uint32_t sbase = smem_u32(smem);
    const int tid  = threadIdx.x;
    const int lane = tid & 31;
    const int wid  = tid >> 5;
    const int bn = blockIdx.x;           // 0..11
    const int bm = blockIdx.y;           // 0..31
    const int sel = bn >> 2;             // 0=Q,1=K,2=V

    const __half* __restrict__ Xb = g_Xc + (size_t)(bm * 128) * KSX;
    const __half* __restrict__ Wb = g_Wc + (size_t)(bn * 128) * KSW;

    const int r0  = tid >> 3;
    const int c16 = tid & 7;
    uint32_t so[4];
    #pragma unroll
    for (int j = 0; j < 4; j++)
        so[j] = swz((uint32_t)((r0 + 32 * j) * 128 + c16 * 16));

    const int wm = wid & 3;
    const int wn = wid >> 2;
    const int g  = lane >> 2;
    const int t  = lane & 3;

    const int a_row = wm * 32 + (lane & 15);
    const int a_kb  = (lane >> 4) * 16;
    const int b_row = wn * 64 + (lane & 7) + (lane >> 4) * 8;
    const int b_kb  = ((lane >> 3) & 1) * 16;

    float acc[2][8][4];
    #pragma unroll
    for (int i = 0; i < 2; i++)
        #pragma unroll
        for (int j = 0; j < 8; j++)
            #pragma unroll
            for (int q = 0; q < 4; q++) acc[i][j][q] = 0.f;

    #pragma unroll
    for (int s = 0; s < STAGES - 1; s++) {
        uint32_t sA = sbase + s * STAGE_BYTES;
        uint32_t sB = sA + ATILE;
        const __half* gA = Xb + (size_t)s * KC + c16 * 8;
        const __half* gB = Wb + (size_t)s * KC + c16 * 8;
        #pragma unroll
        for (int j = 0; j < 4; j++) {
            cp16(sA + so[j], gA + (size_t)(r0 + 32 * j) * KSX);
            cp16(sB + so[j], gB + (size_t)(r0 + 32 * j) * KSW);
        }
        CP_COMMIT();
    }

    for (int i = 0; i < NCHUNK; i++) {
        CP_WAIT(STAGES - 2);
        __syncthreads();

        const int nxt = i + STAGES - 1;
        if (nxt < NCHUNK) {
            const int st = nxt % STAGES;
            uint32_t sA = sbase + st * STAGE_BYTES;
            uint32_t sB = sA + ATILE;
            const __half* gA = Xb + (size_t)nxt * KC + c16 * 8;
            const __half* gB = Wb + (size_t)nxt * KC + c16 * 8;
            #pragma unroll
            for (int j = 0; j < 4; j++) {
                cp16(sA + so[j], gA + (size_t)(r0 + 32 * j) * KSX);
                cp16(sB + so[j], gB + (size_t)(r0 + 32 * j) * KSW);
            }
        }
        CP_COMMIT();

        const uint32_t sA = sbase + (i % STAGES) * STAGE_BYTES;
        const uint32_t sB = sA + ATILE;
        #pragma unroll
        for (int k16 = 0; k16 < 4; k16++) {
            uint32_t af[2][4];
            #pragma unroll
            for (int mt = 0; mt < 2; mt++) {
                uint32_t addr = sA + swz((uint32_t)((a_row + mt * 16) * 128
                                                    + k16 * 32 + a_kb));
                ldmx4(af[mt][0], af[mt][1], af[mt][2], af[mt][3], addr);
            }
            uint32_t bf[8][2];
            #pragma unroll
            for (int nt2 = 0; nt2 < 4; nt2++) {
                uint32_t addr = sB + swz((uint32_t)((b_row + nt2 * 16) * 128
                                                    + k16 * 32 + b_kb));
                uint32_t q0, q1, q2, q3;
                ldmx4(q0, q1, q2, q3, addr);
                bf[nt2 * 2 + 0][0] = q0; bf[nt2 * 2 + 0][1] = q1;
                bf[nt2 * 2 + 1][0] = q2; bf[nt2 * 2 + 1][1] = q3;
            }
            #pragma unroll
            for (int mt = 0; mt < 2; mt++)
                #pragma unroll
                for (int nt = 0; nt < 8; nt++)
                    mma16816(acc[mt][nt], af[mt], bf[nt][0], bf[nt][1]);
        }
    }

    const int nbase = (bn & 3) * 128;
    const float* __restrict__ bia = (sel == 0) ? bq : (sel == 1) ? bk : bv;
    float* __restrict__ dst = (sel == 0) ? g_Q : (sel == 1) ? g_K : g_V;
    const int head = (nbase + wn * 64) >> 6;
    const float scale = (sel == 0) ? (1.0f / (8.0f * expf(beta[head]))) : 1.0f;

    #pragma unroll
    for (int mt = 0; mt < 2; mt++) {
        const int m0 = bm * 128 + wm * 32 + mt * 16 + g;
        #pragma unroll
        for (int nt = 0; nt < 8; nt++) {
            const int nm   = nbase + wn * 64 + nt * 8 + t * 2;
            const int dcol = nm & 63;
            const float b0v = bia[nm], b1v = bia[nm + 1];
            #pragma unroll
            for (int half = 0; half < 2; half++) {
                const int m = m0 + half * 8;
                const int s_idx = m >> 1;
                const int b_idx = m & 1;
                float2 o;
                o.x = (acc[mt][nt][half * 2 + 0] + b0v) * scale;
                o.y = (acc[mt][nt][half * 2 + 1] + b1v) * scale;
                *(float2*)&dst[((size_t)(b_idx * NHEADS + head) * S_LEN + s_idx)
                               * DHEAD + dcol] = o;
            }
        }
    }
}

// ---------------------------------------------------------------------------
// Kernel C: dilation pass 0 reduction; last block per z combines partials
// AND computes the 32 window coefficients c[z][*] using exact fp32 g_Qw.
// ---------------------------------------------------------------------------
__global__ __launch_bounds__(256) void reduce_kv(const float* __restrict__ beta)
{
    const int z = blockIdx.x;
    const int c = blockIdx.y;
    const int t = threadIdx.x;
    const int squad = t >> 2;
    const int dpart = (t & 3) * 16;

    const float* __restrict__ Q = g_Q + (size_t)z * S_LEN * DHEAD + dpart;
    const float* __restrict__ K = g_K + (size_t)z * S_LEN * DHEAD + dpart;
    const float* __restrict__ V = g_V + (size_t)z * S_LEN * DHEAD + dpart;

    float4 k2[4] = {}, v2[4] = {};
    const int s0 = c * 128;

    #pragma unroll
    for (int it = 0; it < 2; it++) {
        const size_t base = (size_t)(s0 + it * 64 + squad) * DHEAD;
        float4 q4[4], k4[4], v4[4];
        #pragma unroll
        for (int j = 0; j < 4; j++) {
            q4[j] = *(const float4*)(Q + base + j * 4);
            k4[j] = *(const float4*)(K + base + j * 4);
            v4[j] = *(const float4*)(V + base + j * 4);
        }
        float dot = 0.f;
        #pragma unroll
        for (int j = 0; j < 4; j++) {
            dot = fmaf(q4[j].x, k4[j].x, dot);
            dot = fmaf(q4[j].y, k4[j].y, dot);
            dot = fmaf(q4[j].z, k4[j].z, dot);
            dot = fmaf(q4[j].w, k4[j].w, dot);
        }
        dot += __shfl_xor_sync(0xFFFFFFFFu, dot, 1);
        dot += __shfl_xor_sync(0xFFFFFFFFu, dot, 2);
        const float w = 1.0f / (1.0f + expf(-dot));
        #pragma unroll
        for (int j = 0; j < 4; j++) {
            k2[j].x = fmaf(w, k4[j].x, k2[j].x);
            k2[j].y = fmaf(w, k4[j].y, k2[j].y);
            k2[j].z = fmaf(w, k4[j].z, k2[j].z);
            k2[j].w = fmaf(w, k4[j].w, k2[j].w);
            v2[j].x = fmaf(w, v4[j].x, v2[j].x);
            v2[j].y = fmaf(w, v4[j].y, v2[j].y);
            v2[j].z = fmaf(w, v4[j].z, v2[j].z);
            v2[j].w = fmaf(w, v4[j].w, v2[j].w);
        }
    }

    __shared__ __align__(16) float sk[64][64];
    __shared__ __align__(16) float sv[64][64];
    #pragma unroll
    for (int j = 0; j < 4; j++) {
        *(float4*)&sk[squad][dpart + j * 4] = k2[j];
        *(float4*)&sv[squad][dpart + j * 4] = v2[j];
    }
    __syncthreads();

    if (t < 128) {
        const int d = t & 63;
        float acc = 0.f;
        if (t < 64) {
            #pragma unroll 8
            for (int sq = 0; sq < 64; sq++) acc += sk[sq][d];
            g_k2p[(z * RCHUNK + c) * DHEAD + d] = acc;
        } else {
            #pragma unroll 8
            for (int sq = 0; sq < 64; sq++) acc += sv[sq][d];
            g_v2p[(z * RCHUNK + c) * DHEAD + d] = acc;
        }
    }
    __syncthreads();

    // Last block per z: combine partials, then compute c[z][*].
    __shared__ int s_last;
    __shared__ __align__(16) float s_k2f[DHEAD];
    __shared__ __align__(16) float s_scr[NWIN];
    if (t == 0) {
        __threadfence();
        const int old = atomicAdd(&g_cnt[z], 1);
        s_last = ((old & (RCHUNK - 1)) == (RCHUNK - 1)) ? 1 : 0;
        if (s_last) __threadfence();
    }
    __syncthreads();
    if (s_last) {
        if (t < 128) {
            const int d = t & 63;
            float acc = 0.f;
            if (t < 64) {
                #pragma unroll
                for (int cc = 0; cc < RCHUNK; cc++)
                    acc += g_k2p[(z * RCHUNK + cc) * DHEAD + d];
                g_k2[z * DHEAD + d] = acc;
                s_k2f[d] = acc;
            } else {
                #pragma unroll
                for (int cc = 0; cc < RCHUNK; cc++)
                    acc += g_v2p[(z * RCHUNK + cc) * DHEAD + d];
                g_v2[z * DHEAD + d] = acc;
            }
        }
        __syncthreads();

        const int h = z & 7;
        const int b = z >> 3;
        const float rscale = 1.0f / (8.0f * expf(beta[h]));

        {   // scores from exact fp32 window-q: w = t>>3, part = t&7 (8 dims)
            const int w = t >> 3, part = t & 7;
            const float* __restrict__ q =
                g_Qw + ((size_t)(b * NWIN + w)) * DMODEL + h * DHEAD + part * 8;
            const float4 q0 = *(const float4*)q;
            const float4 q1 = *(const float4*)(q + 4);
            const float4 k0 = *(const float4*)&s_k2f[part * 8];
            const float4 k1 = *(const float4*)&s_k2f[part * 8 + 4];
            float s = q0.x * k0.x + q0.y * k0.y + q0.z * k0.z + q0.w * k0.w
                    + q1.x * k1.x + q1.y * k1.y + q1.z * k1.z + q1.w * k1.w;
            s += __shfl_xor_sync(0xFFFFFFFFu, s, 1);
            s += __shfl_xor_sync(0xFFFFFFFFu, s, 2);
            s += __shfl_xor_sync(0xFFFFFFFFu, s, 4);
            if (part == 0) s_scr[w] = s * rscale;
        }
        __syncthreads();

        if (t < 32) {
            float s = s_scr[t];
            float mx = s;
            #pragma unroll
            for (int off = 16; off; off >>= 1)
                mx = fmaxf(mx, __shfl_xor_sync(0xFFFFFFFFu, mx, off));
            mx = fmaxf(mx, 0.f);
            const float e = expf(s - mx);
            float sum = e;
            #pragma unroll
            for (int off = 16; off; off >>= 1)
                sum += __shfl_xor_sync(0xFFFFFFFFu, sum, off);
            sum += expf(-mx);
            float cc = e / sum;
            if (t == 31) cc += 1.0f;
            g_c[z * NWIN + t] = cc;
        }
    }
}

// ---------------------------------------------------------------------------
// Kernel D: coef_atomic — 256 blocks, block (z, nc) covers n = nc*32..+31.
// ---------------------------------------------------------------------------
__global__ __launch_bounds__(256) void coef_atomic(
    const float* __restrict__ Wo, float* __restrict__ out)
{
    const int tid = threadIdx.x;
    const int z   = blockIdx.x >> 4;
    const int nc  = blockIdx.x & 15;
    const int h   = z & 7;
    const int batch = z >> 3;

    __shared__ __align__(16) float s_v2[DHEAD];
    __shared__ __align__(16) float s_c[NWIN];
    if (tid < DHEAD) s_v2[tid] = g_v2[z * DHEAD + tid];
    else if (tid < DHEAD + NWIN) s_c[tid - DHEAD] = g_c[z * NWIN + (tid - DHEAD)];
    __syncthreads();

    const int warp = tid >> 5;
    const int lane = tid & 31;
    const float2 v2l = *(const float2*)&s_v2[lane * 2];
    const float  cw  = s_c[lane];

    #pragma unroll
    for (int j = 0; j < 4; j++) {
        const int n = nc * 32 + warp * 4 + j;
        const float2 wv = *(const float2*)(Wo + (size_t)n * DMODEL
                                           + h * DHEAD + lane * 2);
        float dot = v2l.x * wv.x + v2l.y * wv.y;
        #pragma unroll
        for (int off = 16; off; off >>= 1)
            dot += __shfl_xor_sync(0xFFFFFFFFu, dot, off);
        atomicAdd(&out[((size_t)((2016 + lane) * BSZ + batch)) * DMODEL + n],
                  cw * dot);
    }
}

// ---------------------------------------------------------------------------
extern "C" void kernel_launch(void* const* d_in, const int* in_sizes, int n_in,
                              void* d_out, int out_size)
{
    const float* x    = (const float*)d_in[0];
    const float* Wq   = (const float*)d_in[1];
    const float* bq   = (const float*)d_in[2];
    const float* Wk   = (const float*)d_in[3];
    const float* bk   = (const float*)d_in[4];
    const float* Wv   = (const float*)d_in[5];
    const float* bv   = (const float*)d_in[6];
    const float* Wo   = (const float*)d_in[7];
    const float* bo   = (const float*)d_in[8];
    const float* beta = (const float*)d_in[9];
    float* out = (float*)d_out;

    cudaFuncSetAttribute(gemm_mma, cudaFuncAttributeMaxDynamicSharedMemorySize,
                         SMEM_BYTES);

    convert_xw<<<K1_BLOCKS, 256>>>(x, Wq, bq, Wk, Wv, out, bo);
    gemm_mma<<<dim3(NTOT / 128, MROWS / 128), 256, SMEM_BYTES>>>(bq, bk, bv, beta);
    reduce_kv<<<dim3(ZB, RCHUNK), 256>>>(beta);
    coef_atomic<<<256, 256>>>(Wo, out);
}

// round 13
// speedup vs baseline: 2.4264x; 2.4264x over previous
#include <cuda_runtime.h>
#include <cuda_fp16.h>
#include <math.h>
#include <stdint.h>

#define S_LEN  2048
#define BSZ    2
#define DMODEL 512
#define NHEADS 8
#define DHEAD  64
#define ZB     (BSZ*NHEADS)          // 16
#define MROWS  (S_LEN*BSZ)           // 4096
#define NWIN   32
#define KSX    512                   // X row: fp16 hi only
#define KSW    512                   // W row: fp16 hi only
#define NTOT   1536                  // Q,K,V columns stacked
#define KC     64                    // K chunk (fp16) = 128B rows
#define NCHUNK 8                     // single-pass fp16
#define STAGES 3
#define ATILE  16384                 // 128 x 64 fp16
#define BTILE  16384
#define STAGE_BYTES (ATILE+BTILE)
#define SMEM_BYTES  (STAGES*STAGE_BYTES)   // 96 KB
#define RCHUNK 16                    // s-chunks per z in reduce_kv

// Kernel-1 block roles
#define XCV_BLOCKS  512              // X convert: 4 float4 / thread
#define WCV_BLOCKS  768              // W convert: 1 float4 / thread
#define FIL_BLOCKS  512              // bias fill of ALL 2048 rows
#define K1_BLOCKS   (XCV_BLOCKS + WCV_BLOCKS + FIL_BLOCKS)   // 1792

// ---------------- static scratch (no cudaMalloc allowed) -------------------
__device__ __align__(16) __half g_Xc[(size_t)MROWS*KSX];  // 4.2 MB
__device__ __align__(16) __half g_Wc[(size_t)NTOT*KSW];   // 1.6 MB
__device__ __align__(16) float g_Q[(size_t)ZB*S_LEN*DHEAD];
__device__ __align__(16) float g_K[(size_t)ZB*S_LEN*DHEAD];
__device__ __align__(16) float g_V[(size_t)ZB*S_LEN*DHEAD];
__device__ __align__(16) float g_k2p[ZB*RCHUNK*DHEAD];
__device__ __align__(16) float g_v2p[ZB*RCHUNK*DHEAD];
__device__ __align__(16) float g_k2[ZB*DHEAD];
__device__ __align__(16) float g_v2[ZB*DHEAD];
__device__ int   g_cnt[ZB];          // replay-safe via &15
__device__ __align__(16) float g_c[ZB*NWIN];

// ---------------- helpers ---------------------------------------------------
__device__ __forceinline__ uint32_t smem_u32(const void* p) {
    uint32_t a;
    asm("{ .reg .u64 t; cvta.to.shared.u64 t, %1; cvt.u32.u64 %0, t; }"
        : "=r"(a) : "l"(p));
    return a;
}
__device__ __forceinline__ uint32_t swz(uint32_t off) {
    return off ^ ((off >> 3) & 0x70);      // SW128
}
__device__ __forceinline__ void cp16(uint32_t saddr, const void* g) {
    asm volatile("cp.async.cg.shared.global [%0], [%1], 16;"
                 :: "r"(saddr), "l"(g) : "memory");
}
#define CP_COMMIT() asm volatile("cp.async.commit_group;" ::: "memory")
#define CP_WAIT(n)  asm volatile("cp.async.wait_group %0;" :: "n"(n) : "memory")

__device__ __forceinline__ void ldmx4(uint32_t& r0, uint32_t& r1,
                                      uint32_t& r2, uint32_t& r3, uint32_t a) {
    asm volatile("ldmatrix.sync.aligned.m8n8.x4.shared.b16 {%0,%1,%2,%3}, [%4];"
                 : "=r"(r0), "=r"(r1), "=r"(r2), "=r"(r3) : "r"(a));
}
__device__ __forceinline__ void mma16816(float* c, const uint32_t* a,
                                         uint32_t b0, uint32_t b1) {
    asm volatile(
        "mma.sync.aligned.m16n8k16.row.col.f32.f16.f16.f32 "
        "{%0,%1,%2,%3}, {%4,%5,%6,%7}, {%8,%9}, {%0,%1,%2,%3};"
        : "+f"(c[0]), "+f"(c[1]), "+f"(c[2]), "+f"(c[3])
        : "r"(a[0]), "r"(a[1]), "r"(a[2]), "r"(a[3]), "r"(b0), "r"(b1));
}

// ---------------------------------------------------------------------------
// Kernel A:
//   [0,512)       : X -> fp16 (hi only), 4 float4/thread
//   [512,1280)    : W -> fp16 (hi only)
//   [1280,1792)   : bias fill of ALL 2048 output rows (atomic base)
// ---------------------------------------------------------------------------
__global__ __launch_bounds__(256) void convert_xw(
    const float* __restrict__ x,
    const float* __restrict__ Wq, const float* __restrict__ Wk,
    const float* __restrict__ Wv,
    float* __restrict__ out, const float* __restrict__ bo)
{
    const int tid = threadIdx.x;
    const int bid = blockIdx.x;
    const int W4PM = DMODEL / 4;                       // 128 float4 per row

    if (bid < XCV_BLOCKS) {
        #pragma unroll
        for (int j = 0; j < 4; j++) {
            const int tid4 = bid * 1024 + j * 256 + tid;
            const float4 v = ((const float4*)x)[tid4];
            const int m    = tid4 / W4PM;
            const int koff = (tid4 % W4PM) * 4;
            __half2 hi01 = __halves2half2(__float2half_rn(v.x), __float2half_rn(v.y));
            __half2 hi23 = __halves2half2(__float2half_rn(v.z), __float2half_rn(v.w));
            __half2* d0 = (__half2*)(g_Xc + (size_t)m * KSX + koff);
            d0[0] = hi01; d0[1] = hi23;
        }
    } else if (bid < XCV_BLOCKS + WCV_BLOCKS) {
        const int wi   = (bid - XCV_BLOCKS) * 256 + tid;
        const int n    = wi / W4PM;
        const int koff = (wi % W4PM) * 4;
        const int sel  = n >> 9, row = n & 511;
        const float* W = (sel == 0) ? Wq : (sel == 1) ? Wk : Wv;
        const float4 v = *(const float4*)(W + (size_t)row * DMODEL + koff);
        __half2 hi01 = __halves2half2(__float2half_rn(v.x), __float2half_rn(v.y));
        __half2 hi23 = __halves2half2(__float2half_rn(v.z), __float2half_rn(v.w));
        __half2* d0 = (__half2*)(g_Wc + (size_t)n * KSW + koff);
        d0[0] = hi01; d0[1] = hi23;
    } else {
        __shared__ __align__(16) float4 sb[128];
        if (tid < 128) sb[tid] = ((const float4*)bo)[tid];
        __syncthreads();
        const int blk = bid - (XCV_BLOCKS + WCV_BLOCKS);   // 0..511
        float4* out4 = (float4*)out;
        #pragma unroll
        for (int j = 0; j < 4; j++) {
            const int idx = blk * 1024 + j * 256 + tid;
            out4[idx] = sb[idx & 127];
        }
    }
}

// ---------------------------------------------------------------------------
// Kernel B: fp16 warp-MMA GEMM, single pass (8 chunks) for Q, K, V.
// ---------------------------------------------------------------------------
__global__ __launch_bounds__(256, 2) void gemm_mma(
    const float* __restrict__ bq, const float* __restrict__ bk,
    const float* __restrict__ bv, const float* __restrict__ beta)
{
    extern __shared__ __align__(1024) char smem[];
    const uint32_t sbase = smem_u32(smem);
    const int tid  = threadIdx.x;
    const int lane = tid & 31;
    const int wid  = tid >> 5;
    const int bn = blockIdx.x;           // 0..11
    const int bm = blockIdx.y;           // 0..31
    const int sel = bn >> 2;             // 0=Q,1=K,2=V

    const __half* __restrict__ Xb = g_Xc + (size_t)(bm * 128) * KSX;
    const __half* __restrict__ Wb = g_Wc + (size_t)(bn * 128) * KSW;

    const int r0  = tid >> 3;
    const int c16 = tid & 7;
    uint32_t so[4];
    #pragma unroll
    for (int j = 0; j < 4; j++)
        so[j] = swz((uint32_t)((r0 + 32 * j) * 128 + c16 * 16));

    const int wm = wid & 3;
    const int wn = wid >> 2;
    const int g  = lane >> 2;
    const int t  = lane & 3;

    const int a_row = wm * 32 + (lane & 15);
    const int a_kb  = (lane >> 4) * 16;
    const int b_row = wn * 64 + (lane & 7) + (lane >> 4) * 8;
    const int b_kb  = ((lane >> 3) & 1) * 16;

    float acc[2][8][4];
    #pragma unroll
    for (int i = 0; i < 2; i++)
        #pragma unroll
        for (int j = 0; j < 8; j++)
            #pragma unroll
            for (int q = 0; q < 4; q++) acc[i][j][q] = 0.f;

    #pragma unroll
    for (int s = 0; s < STAGES - 1; s++) {
        uint32_t sA = sbase + s * STAGE_BYTES;
        uint32_t sB = sA + ATILE;
        const __half* gA = Xb + (size_t)s * KC + c16 * 8;
        const __half* gB = Wb + (size_t)s * KC + c16 * 8;
        #pragma unroll
        for (int j = 0; j < 4; j++) {
            cp16(sA + so[j], gA + (size_t)(r0 + 32 * j) * KSX);
            cp16(sB + so[j], gB + (size_t)(r0 + 32 * j) * KSW);
        }
        CP_COMMIT();
    }

    for (int i = 0; i < NCHUNK; i++) {
        CP_WAIT(STAGES - 2);
        __syncthreads();

        const int nxt = i + STAGES - 1;
        if (nxt < NCHUNK) {
            const int st = nxt % STAGES;
            uint32_t sA = sbase + st * STAGE_BYTES;
            uint32_t sB = sA + ATILE;
            const __half* gA = Xb + (size_t)nxt * KC + c16 * 8;
            const __half* gB = Wb + (size_t)nxt * KC + c16 * 8;
            #pragma unroll
            for (int j = 0; j < 4; j++) {
                cp16(sA + so[j], gA + (size_t)(r0 + 32 * j) * KSX);
                cp16(sB + so[j], gB + (size_t)(r0 + 32 * j) * KSW);
            }
        }
        CP_COMMIT();

        const uint32_t sA = sbase + (i % STAGES) * STAGE_BYTES;
        const uint32_t sB = sA + ATILE;
        #pragma unroll
        for (int k16 = 0; k16 < 4; k16++) {
            uint32_t af[2][4];
            #pragma unroll
            for (int mt = 0; mt < 2; mt++) {
                uint32_t addr = sA + swz((uint32_t)((a_row + mt * 16) * 128
                                                    + k16 * 32 + a_kb));
                ldmx4(af[mt][0], af[mt][1], af[mt][2], af[mt][3], addr);
            }
            uint32_t bf[8][2];
            #pragma unroll
            for (int nt2 = 0; nt2 < 4; nt2++) {
                uint32_t addr = sB + swz((uint32_t)((b_row + nt2 * 16) * 128
                                                    + k16 * 32 + b_kb));
                uint32_t q0, q1, q2, q3;
                ldmx4(q0, q1, q2, q3, addr);
                bf[nt2 * 2 + 0][0] = q0; bf[nt2 * 2 + 0][1] = q1;
                bf[nt2 * 2 + 1][0] = q2; bf[nt2 * 2 + 1][1] = q3;
            }
            #pragma unroll
            for (int mt = 0; mt < 2; mt++)
                #pragma unroll
                for (int nt = 0; nt < 8; nt++)
                    mma16816(acc[mt][nt], af[mt], bf[nt][0], bf[nt][1]);
        }
    }

    const int nbase = (bn & 3) * 128;
    const float* __restrict__ bia = (sel == 0) ? bq : (sel == 1) ? bk : bv;
    float* __restrict__ dst = (sel == 0) ? g_Q : (sel == 1) ? g_K : g_V;
    const int head = (nbase + wn * 64) >> 6;
    const float scale = (sel == 0) ? (1.0f / (8.0f * expf(beta[head]))) : 1.0f;

    #pragma unroll
    for (int mt = 0; mt < 2; mt++) {
        const int m0 = bm * 128 + wm * 32 + mt * 16 + g;
        #pragma unroll
        for (int nt = 0; nt < 8; nt++) {
            const int nm   = nbase + wn * 64 + nt * 8 + t * 2;
            const int dcol = nm & 63;
            const float b0v = bia[nm], b1v = bia[nm + 1];
            #pragma unroll
            for (int half = 0; half < 2; half++) {
                const int m = m0 + half * 8;
                const int s_idx = m >> 1;
                const int b_idx = m & 1;
                float2 o;
                o.x = (acc[mt][nt][half * 2 + 0] + b0v) * scale;
                o.y = (acc[mt][nt][half * 2 + 1] + b1v) * scale;
                *(float2*)&dst[((size_t)(b_idx * NHEADS + head) * S_LEN + s_idx)
                               * DHEAD + dcol] = o;
            }
        }
    }
}

// ---------------------------------------------------------------------------
// Kernel C: dilation pass 0 reduction; last block per z combines partials,
// then computes EXACT window scores via  u = Wq_h^T k2  and  s_w = x[s_w]·u:
//   score_w = rscale * ( x[s_w,b] · u  +  bq_h · k2 )
// followed by sink-softmax -> g_c.
// ---------------------------------------------------------------------------
__global__ __launch_bounds__(256) void reduce_kv(
    const float* __restrict__ x, const float* __restrict__ Wq,
    const float* __restrict__ bq, const float* __restrict__ beta)
{
    const int z = blockIdx.x;
    const int c = blockIdx.y;
    const int t = threadIdx.x;
    const int squad = t >> 2;
    const int dpart = (t & 3) * 16;

    const float* __restrict__ Q = g_Q + (size_t)z * S_LEN * DHEAD + dpart;
    const float* __restrict__ K = g_K + (size_t)z * S_LEN * DHEAD + dpart;
    const float* __restrict__ V = g_V + (size_t)z * S_LEN * DHEAD + dpart;

    float4 k2[4] = {}, v2[4] = {};
    const int s0 = c * 128;

    #pragma unroll
    for (int it = 0; it < 2; it++) {
        const size_t base = (size_t)(s0 + it * 64 + squad) * DHEAD;
        float4 q4[4], k4[4], v4[4];
        #pragma unroll
        for (int j = 0; j < 4; j++) {
            q4[j] = *(const float4*)(Q + base + j * 4);
            k4[j] = *(const float4*)(K + base + j * 4);
            v4[j] = *(const float4*)(V + base + j * 4);
        }
        float dot = 0.f;
        #pragma unroll
        for (int j = 0; j < 4; j++) {
            dot = fmaf(q4[j].x, k4[j].x, dot);
            dot = fmaf(q4[j].y, k4[j].y, dot);
            dot = fmaf(q4[j].z, k4[j].z, dot);
            dot = fmaf(q4[j].w, k4[j].w, dot);
        }
        dot += __shfl_xor_sync(0xFFFFFFFFu, dot, 1);
        dot += __shfl_xor_sync(0xFFFFFFFFu, dot, 2);
        const float w = 1.0f / (1.0f + expf(-dot));
        #pragma unroll
        for (int j = 0; j < 4; j++) {
            k2[j].x = fmaf(w, k4[j].x, k2[j].x);
            k2[j].y = fmaf(w, k4[j].y, k2[j].y);
            k2[j].z = fmaf(w, k4[j].z, k2[j].z);
            k2[j].w = fmaf(w, k4[j].w, k2[j].w);
            v2[j].x = fmaf(w, v4[j].x, v2[j].x);
            v2[j].y = fmaf(w, v4[j].y, v2[j].y);
            v2[j].z = fmaf(w, v4[j].z, v2[j].z);
            v2[j].w = fmaf(w, v4[j].w, v2[j].w);
        }
    }

    __shared__ __align__(16) float sk[64][64];
    __shared__ __align__(16) float sv[64][64];
    #pragma unroll
    for (int j = 0; j < 4; j++) {
        *(float4*)&sk[squad][dpart + j * 4] = k2[j];
        *(float4*)&sv[squad][dpart + j * 4] = v2[j];
    }
    __syncthreads();

    if (t < 128) {
        const int d = t & 63;
        float acc = 0.f;
        if (t < 64) {
            #pragma unroll 8
            for (int sq = 0; sq < 64; sq++) acc += sk[sq][d];
            g_k2p[(z * RCHUNK + c) * DHEAD + d] = acc;
        } else {
            #pragma unroll 8
            for (int sq = 0; sq < 64; sq++) acc += sv[sq][d];
            g_v2p[(z * RCHUNK + c) * DHEAD + d] = acc;
        }
    }
    __syncthreads();

    // Last block per z: combine partials; exact window scores; softmax.
    __shared__ int s_last;
    __shared__ __align__(16) float s_k2f[DHEAD];
    __shared__ __align__(16) float s_u[DMODEL];
    __shared__ __align__(16) float s_scr[NWIN];
    __shared__ float s_bconst;
    if (t == 0) {
        __threadfence();
        const int old = atomicAdd(&g_cnt[z], 1);
        s_last = ((old & (RCHUNK - 1)) == (RCHUNK - 1)) ? 1 : 0;
        if (s_last) __threadfence();
    }
    __syncthreads();
    if (!s_last) return;

    if (t < 128) {
        const int d = t & 63;
        float acc = 0.f;
        if (t < 64) {
            #pragma unroll
            for (int cc = 0; cc < RCHUNK; cc++)
                acc += g_k2p[(z * RCHUNK + cc) * DHEAD + d];
            g_k2[z * DHEAD + d] = acc;
            s_k2f[d] = acc;
        } else {
            #pragma unroll
            for (int cc = 0; cc < RCHUNK; cc++)
                acc += g_v2p[(z * RCHUNK + cc) * DHEAD + d];
            g_v2[z * DHEAD + d] = acc;
        }
    }
    __syncthreads();

    const int h = z & 7;
    const int b = z >> 3;

    // u[k] = sum_d Wq[64h+d, k] * k2[d]   (lanes coalesced over k)
    {
        float u0 = 0.f, u1 = 0.f;
        const float* __restrict__ Wqh = Wq + (size_t)(h * DHEAD) * DMODEL;
        #pragma unroll 8
        for (int d = 0; d < DHEAD; d++) {
            const float kv = s_k2f[d];
            u0 = fmaf(Wqh[(size_t)d * DMODEL + t],        kv, u0);
            u1 = fmaf(Wqh[(size_t)d * DMODEL + 256 + t],  kv, u1);
        }
        s_u[t] = u0;
        s_u[256 + t] = u1;
    }
    // bconst = bq_h . k2   (warp 0)
    if (t < 32) {
        float p = bq[h * DHEAD + t] * s_k2f[t]
                + bq[h * DHEAD + 32 + t] * s_k2f[32 + t];
        #pragma unroll
        for (int off = 16; off; off >>= 1)
            p += __shfl_xor_sync(0xFFFFFFFFu, p, off);
        if (t == 0) s_bconst = p;
    }
    __syncthreads();

    const float rscale = 1.0f / (8.0f * expf(beta[h]));

    {   // scores: w = t>>3 (0..31), part = t&7 handles 64 k-elements
        const int w = t >> 3, part = t & 7;
        const float4* __restrict__ xrow =
            (const float4*)(x + ((size_t)(64 * w + 63) * BSZ + b) * DMODEL) + part * 16;
        const float4* __restrict__ u4 = (const float4*)s_u + part * 16;
        float s = 0.f;
        #pragma unroll
        for (int j = 0; j < 16; j++) {
            const float4 xv = xrow[j];
            const float4 uv = u4[j];
            s = fmaf(xv.x, uv.x, s); s = fmaf(xv.y, uv.y, s);
            s = fmaf(xv.z, uv.z, s); s = fmaf(xv.w, uv.w, s);
        }
        s += __shfl_xor_sync(0xFFFFFFFFu, s, 1);
        s += __shfl_xor_sync(0xFFFFFFFFu, s, 2);
        s += __shfl_xor_sync(0xFFFFFFFFu, s, 4);
        if (part == 0) s_scr[w] = (s + s_bconst) * rscale;
    }
    __syncthreads();

    if (t < 32) {
        float s = s_scr[t];
        float mx = s;
        #pragma unroll
        for (int off = 16; off; off >>= 1)
            mx = fmaxf(mx, __shfl_xor_sync(0xFFFFFFFFu, mx, off));
        mx = fmaxf(mx, 0.f);
        const float e = expf(s - mx);
        float sum = e;
        #pragma unroll
        for (int off = 16; off; off >>= 1)
            sum += __shfl_xor_sync(0xFFFFFFFFu, sum, off);
        sum += expf(-mx);
        float cc = e / sum;
        if (t == 31) cc += 1.0f;
        g_c[z * NWIN + t] = cc;
    }
}

// ---------------------------------------------------------------------------
// Kernel D: coef_atomic — 256 blocks, block (z, nc) covers n = nc*32..+31.
// dot = v2[z] . Wo[n, h*64:+64]; lane w adds c[z][w]*dot into out row 2016+w.
// ---------------------------------------------------------------------------
__global__ __launch_bounds__(256) void coef_atomic(
    const float* __restrict__ Wo, float* __restrict__ out)
{
    const int tid = threadIdx.x;
    const int z   = blockIdx.x >> 4;
    const int nc  = blockIdx.x & 15;
    const int h   = z & 7;
    const int batch = z >> 3;

    __shared__ __align__(16) float s_v2[DHEAD];
    __shared__ __align__(16) float s_c[NWIN];
    if (tid < DHEAD) s_v2[tid] = g_v2[z * DHEAD + tid];
    else if (tid < DHEAD + NWIN) s_c[tid - DHEAD] = g_c[z * NWIN + (tid - DHEAD)];
    __syncthreads();

    const int warp = tid >> 5;
    const int lane = tid & 31;
    const float2 v2l = *(const float2*)&s_v2[lane * 2];
    const float  cw  = s_c[lane];

    #pragma unroll
    for (int j = 0; j < 4; j++) {
        const int n = nc * 32 + warp * 4 + j;
        const float2 wv = *(const float2*)(Wo + (size_t)n * DMODEL
                                           + h * DHEAD + lane * 2);
        float dot = v2l.x * wv.x + v2l.y * wv.y;
        #pragma unroll
        for (int off = 16; off; off >>= 1)
            dot += __shfl_xor_sync(0xFFFFFFFFu, dot, off);
        atomicAdd(&out[((size_t)((2016 + lane) * BSZ + batch)) * DMODEL + n],
                  cw * dot);
    }
}

// ---------------------------------------------------------------------------
extern "C" void kernel_launch(void* const* d_in, const int* in_sizes, int n_in,
                              void* d_out, int out_size)
{
    const float* x    = (const float*)d_in[0];
    const float* Wq   = (const float*)d_in[1];
    const float* bq   = (const float*)d_in[2];
    const float* Wk   = (const float*)d_in[3];
    const float* bk   = (const float*)d_in[4];
    const float* Wv   = (const float*)d_in[5];
    const float* bv   = (const float*)d_in[6];
    const float* Wo   = (const float*)d_in[7];
    const float* bo   = (const float*)d_in[8];
    const float* beta = (const float*)d_in[9];
    float* out = (float*)d_out;

    cudaFuncSetAttribute(gemm_mma, cudaFuncAttributeMaxDynamicSharedMemorySize,
                         SMEM_BYTES);

    convert_xw<<<K1_BLOCKS, 256>>>(x, Wq, Wk, Wv, out, bo);
    gemm_mma<<<dim3(NTOT / 128, MROWS / 128), 256, SMEM_BYTES>>>(bq, bk, bv, beta);
    reduce_kv<<<dim3(ZB, RCHUNK), 256>>>(x, Wq, bq, beta);
    coef_atomic<<<256, 256>>>(Wo, out);
}

// round 14
// speedup vs baseline: 2.4444x; 1.0075x over previous
#include <cuda_runtime.h>
#include <cuda_fp16.h>
#include <math.h>
#include <stdint.h>

#define S_LEN  2048
#define BSZ    2
#define DMODEL 512
#define NHEADS 8
#define DHEAD  64
#define ZB     (BSZ*NHEADS)          // 16
#define MROWS  (S_LEN*BSZ)           // 4096
#define NWIN   32
#define KSX    512                   // X row: fp16 hi only
#define KSW    512                   // W row: fp16 hi only
#define NTOT   1536                  // Q,K,V columns stacked
#define KC     64                    // K chunk (fp16) = 128B rows
#define NCHUNK 8                     // single-pass fp16
#define STAGES 3
#define ATILE  16384                 // 128 x 64 fp16
#define BTILE  16384
#define STAGE_BYTES (ATILE+BTILE)
#define SMEM_BYTES  (STAGES*STAGE_BYTES)   // 96 KB
#define RCHUNK 16                    // s-chunks per z in reduce_kv

// Kernel-1 block roles
#define XCV_BLOCKS  512              // X convert: 4 float4 / thread
#define WCV_BLOCKS  768              // W convert: 1 float4 / thread
#define FIL_BLOCKS  512              // bias fill of ALL 2048 rows
#define K1_BLOCKS   (XCV_BLOCKS + WCV_BLOCKS + FIL_BLOCKS)   // 1792

// ---------------- static scratch (no cudaMalloc allowed) -------------------
__device__ __align__(16) __half g_Xc[(size_t)MROWS*KSX];  // 4.2 MB
__device__ __align__(16) __half g_Wc[(size_t)NTOT*KSW];   // 1.6 MB
__device__ __align__(16) __half g_Qh[(size_t)ZB*S_LEN*DHEAD];  // fp16 Q
__device__ __align__(16) __half g_Kh[(size_t)ZB*S_LEN*DHEAD];  // fp16 K
__device__ __align__(16) __half g_Vh[(size_t)ZB*S_LEN*DHEAD];  // fp16 V
__device__ __align__(16) float g_k2p[ZB*RCHUNK*DHEAD];
__device__ __align__(16) float g_v2p[ZB*RCHUNK*DHEAD];
__device__ __align__(16) float g_k2[ZB*DHEAD];
__device__ __align__(16) float g_v2[ZB*DHEAD];
__device__ int   g_cnt[ZB];          // replay-safe via &15
__device__ __align__(16) float g_c[ZB*NWIN];

// ---------------- helpers ---------------------------------------------------
__device__ __forceinline__ uint32_t smem_u32(const void* p) {
    uint32_t a;
    asm("{ .reg .u64 t; cvta.to.shared.u64 t, %1; cvt.u32.u64 %0, t; }"
        : "=r"(a) : "l"(p));
    return a;
}
__device__ __forceinline__ uint32_t swz(uint32_t off) {
    return off ^ ((off >> 3) & 0x70);      // SW128
}
__device__ __forceinline__ void cp16(uint32_t saddr, const void* g) {
    asm volatile("cp.async.cg.shared.global [%0], [%1], 16;"
                 :: "r"(saddr), "l"(g) : "memory");
}
#define CP_COMMIT() asm volatile("cp.async.commit_group;" ::: "memory")
#define CP_WAIT(n)  asm volatile("cp.async.wait_group %0;" :: "n"(n) : "memory")

__device__ __forceinline__ void ldmx4(uint32_t& r0, uint32_t& r1,
                                      uint32_t& r2, uint32_t& r3, uint32_t a) {
    asm volatile("ldmatrix.sync.aligned.m8n8.x4.shared.b16 {%0,%1,%2,%3}, [%4];"
                 : "=r"(r0), "=r"(r1), "=r"(r2), "=r"(r3) : "r"(a));
}
__device__ __forceinline__ void mma16816(float* c, const uint32_t* a,
                                         uint32_t b0, uint32_t b1) {
    asm volatile(
        "mma.sync.aligned.m16n8k16.row.col.f32.f16.f16.f32 "
        "{%0,%1,%2,%3}, {%4,%5,%6,%7}, {%8,%9}, {%0,%1,%2,%3};"
        : "+f"(c[0]), "+f"(c[1]), "+f"(c[2]), "+f"(c[3])
        : "r"(a[0]), "r"(a[1]), "r"(a[2]), "r"(a[3]), "r"(b0), "r"(b1));
}
// Load 16 consecutive halves (32B, 16B-aligned) and widen to float[16].
__device__ __forceinline__ void ld16h(const __half* p, float* f) {
    const uint4 u0 = *(const uint4*)p;
    const uint4 u1 = *(const uint4*)(p + 8);
    const __half2* h0 = (const __half2*)&u0;
    const __half2* h1 = (const __half2*)&u1;
    #pragma unroll
    for (int i = 0; i < 4; i++) {
        const float2 a = __half22float2(h0[i]);
        f[i * 2] = a.x; f[i * 2 + 1] = a.y;
    }
    #pragma unroll
    for (int i = 0; i < 4; i++) {
        const float2 a = __half22float2(h1[i]);
        f[8 + i * 2] = a.x; f[8 + i * 2 + 1] = a.y;
    }
}

// ---------------------------------------------------------------------------
// Kernel A:
//   [0,512)       : X -> fp16 (hi only), 4 float4/thread
//   [512,1280)    : W -> fp16 (hi only)
//   [1280,1792)   : bias fill of ALL 2048 output rows (atomic base)
// ---------------------------------------------------------------------------
__global__ __launch_bounds__(256) void convert_xw(
    const float* __restrict__ x,
    const float* __restrict__ Wq, const float* __restrict__ Wk,
    const float* __restrict__ Wv,
    float* __restrict__ out, const float* __restrict__ bo)
{
    const int tid = threadIdx.x;
    const int bid = blockIdx.x;
    const int W4PM = DMODEL / 4;                       // 128 float4 per row

    if (bid < XCV_BLOCKS) {
        #pragma unroll
        for (int j = 0; j < 4; j++) {
            const int tid4 = bid * 1024 + j * 256 + tid;
            const float4 v = ((const float4*)x)[tid4];
            const int m    = tid4 / W4PM;
            const int koff = (tid4 % W4PM) * 4;
            __half2 hi01 = __halves2half2(__float2half_rn(v.x), __float2half_rn(v.y));
            __half2 hi23 = __halves2half2(__float2half_rn(v.z), __float2half_rn(v.w));
            __half2* d0 = (__half2*)(g_Xc + (size_t)m * KSX + koff);
            d0[0] = hi01; d0[1] = hi23;
        }
    } else if (bid < XCV_BLOCKS + WCV_BLOCKS) {
        const int wi   = (bid - XCV_BLOCKS) * 256 + tid;
        const int n    = wi / W4PM;
        const int koff = (wi % W4PM) * 4;
        const int sel  = n >> 9, row = n & 511;
        const float* W = (sel == 0) ? Wq : (sel == 1) ? Wk : Wv;
        const float4 v = *(const float4*)(W + (size_t)row * DMODEL + koff);
        __half2 hi01 = __halves2half2(__float2half_rn(v.x), __float2half_rn(v.y));
        __half2 hi23 = __halves2half2(__float2half_rn(v.z), __float2half_rn(v.w));
        __half2* d0 = (__half2*)(g_Wc + (size_t)n * KSW + koff);
        d0[0] = hi01; d0[1] = hi23;
    } else {
        __shared__ __align__(16) float4 sb[128];
        if (tid < 128) sb[tid] = ((const float4*)bo)[tid];
        __syncthreads();
        const int blk = bid - (XCV_BLOCKS + WCV_BLOCKS);   // 0..511
        float4* out4 = (float4*)out;
        #pragma unroll
        for (int j = 0; j < 4; j++) {
            const int idx = blk * 1024 + j * 256 + tid;
            out4[idx] = sb[idx & 127];
        }
    }
}

// ---------------------------------------------------------------------------
// Kernel B: fp16 warp-MMA GEMM, single pass (8 chunks); outputs fp16 Q/K/V.
// ---------------------------------------------------------------------------
__global__ __launch_bounds__(256, 2) void gemm_mma(
    const float* __restrict__ bq, const float* __restrict__ bk,
    const float* __restrict__ bv, const float* __restrict__ beta)
{
    extern __shared__ __align__(1024) char smem[];
    const uint32_t sbase = smem_u32(smem);
    const int tid  = threadIdx.x;
    const int lane = tid & 31;
    const int wid  = tid >> 5;
    const int bn = blockIdx.x;           // 0..11
    const int bm = blockIdx.y;           // 0..31
    const int sel = bn >> 2;             // 0=Q,1=K,2=V

    const __half* __restrict__ Xb = g_Xc + (size_t)(bm * 128) * KSX;
    const __half* __restrict__ Wb = g_Wc + (size_t)(bn * 128) * KSW;

    const int r0  = tid >> 3;
    const int c16 = tid & 7;
    uint32_t so[4];
    #pragma unroll
    for (int j = 0; j < 4; j++)
        so[j] = swz((uint32_t)((r0 + 32 * j) * 128 + c16 * 16));

    const int wm = wid & 3;
    const int wn = wid >> 2;
    const int g  = lane >> 2;
    const int t  = lane & 3;

    const int a_row = wm * 32 + (lane & 15);
    const int a_kb  = (lane >> 4) * 16;
    const int b_row = wn * 64 + (lane & 7) + (lane >> 4) * 8;
    const int b_kb  = ((lane >> 3) & 1) * 16;

    float acc[2][8][4];
    #pragma unroll
    for (int i = 0; i < 2; i++)
        #pragma unroll
        for (int j = 0; j < 8; j++)
            #pragma unroll
            for (int q = 0; q < 4; q++) acc[i][j][q] = 0.f;

    #pragma unroll
    for (int s = 0; s < STAGES - 1; s++) {
        uint32_t sA = sbase + s * STAGE_BYTES;
        uint32_t sB = sA + ATILE;
        const __half* gA = Xb + (size_t)s * KC + c16 * 8;
        const __half* gB = Wb + (size_t)s * KC + c16 * 8;
        #pragma unroll
        for (int j = 0; j < 4; j++) {
            cp16(sA + so[j], gA + (size_t)(r0 + 32 * j) * KSX);
            cp16(sB + so[j], gB + (size_t)(r0 + 32 * j) * KSW);
        }
        CP_COMMIT();
    }

    for (int i = 0; i < NCHUNK; i++) {
        CP_WAIT(STAGES - 2);
        __syncthreads();

        const int nxt = i + STAGES - 1;
        if (nxt < NCHUNK) {
            const int st = nxt % STAGES;
            uint32_t sA = sbase + st * STAGE_BYTES;
            uint32_t sB = sA + ATILE;
            const __half* gA = Xb + (size_t)nxt * KC + c16 * 8;
            const __half* gB = Wb + (size_t)nxt * KC + c16 * 8;
            #pragma unroll
            for (int j = 0; j < 4; j++) {
                cp16(sA + so[j], gA + (size_t)(r0 + 32 * j) * KSX);
                cp16(sB + so[j], gB + (size_t)(r0 + 32 * j) * KSW);
            }
        }
        CP_COMMIT();

        const uint32_t sA = sbase + (i % STAGES) * STAGE_BYTES;
        const uint32_t sB = sA + ATILE;
        #pragma unroll
        for (int k16 = 0; k16 < 4; k16++) {
            uint32_t af[2][4];
            #pragma unroll
            for (int mt = 0; mt < 2; mt++) {
                uint32_t addr = sA + swz((uint32_t)((a_row + mt * 16) * 128
                                                    + k16 * 32 + a_kb));
                ldmx4(af[mt][0], af[mt][1], af[mt][2], af[mt][3], addr);
            }
            uint32_t bf[8][2];
            #pragma unroll
            for (int nt2 = 0; nt2 < 4; nt2++) {
                uint32_t addr = sB + swz((uint32_t)((b_row + nt2 * 16) * 128
                                                    + k16 * 32 + b_kb));
                uint32_t q0, q1, q2, q3;
                ldmx4(q0, q1, q2, q3, addr);
                bf[nt2 * 2 + 0][0] = q0; bf[nt2 * 2 + 0][1] = q1;
                bf[nt2 * 2 + 1][0] = q2; bf[nt2 * 2 + 1][1] = q3;
            }
            #pragma unroll
            for (int mt = 0; mt < 2; mt++)
                #pragma unroll
                for (int nt = 0; nt < 8; nt++)
                    mma16816(acc[mt][nt], af[mt], bf[nt][0], bf[nt][1]);
        }
    }

    const int nbase = (bn & 3) * 128;
    const float* __restrict__ bia = (sel == 0) ? bq : (sel == 1) ? bk : bv;
    __half* __restrict__ dst = (sel == 0) ? g_Qh : (sel == 1) ? g_Kh : g_Vh;
    const int head = (nbase + wn * 64) >> 6;
    const float scale = (sel == 0) ? (1.0f / (8.0f * expf(beta[head]))) : 1.0f;

    #pragma unroll
    for (int mt = 0; mt < 2; mt++) {
        const int m0 = bm * 128 + wm * 32 + mt * 16 + g;
        #pragma unroll
        for (int nt = 0; nt < 8; nt++) {
            const int nm   = nbase + wn * 64 + nt * 8 + t * 2;
            const int dcol = nm & 63;
            const float b0v = bia[nm], b1v = bia[nm + 1];
            #pragma unroll
            for (int half = 0; half < 2; half++) {
                const int m = m0 + half * 8;
                const int s_idx = m >> 1;
                const int b_idx = m & 1;
                const float ox = (acc[mt][nt][half * 2 + 0] + b0v) * scale;
                const float oy = (acc[mt][nt][half * 2 + 1] + b1v) * scale;
                *(__half2*)&dst[((size_t)(b_idx * NHEADS + head) * S_LEN + s_idx)
                                * DHEAD + dcol] = __floats2half2_rn(ox, oy);
            }
        }
    }
}

// ---------------------------------------------------------------------------
// Kernel C: dilation pass 0 reduction over fp16 Q/K/V; last block per z
// combines partials, then EXACT window scores via u = Wq_h^T k2:
//   score_w = rscale * ( x[s_w,b]·u + bq_h·k2 ),  sink-softmax -> g_c.
// ---------------------------------------------------------------------------
__global__ __launch_bounds__(256) void reduce_kv(
    const float* __restrict__ x, const float* __restrict__ Wq,
    const float* __restrict__ bq, const float* __restrict__ beta)
{
    const int z = blockIdx.x;
    const int c = blockIdx.y;
    const int t = threadIdx.x;
    const int squad = t >> 2;
    const int dpart = (t & 3) * 16;

    const __half* __restrict__ Q = g_Qh + (size_t)z * S_LEN * DHEAD + dpart;
    const __half* __restrict__ K = g_Kh + (size_t)z * S_LEN * DHEAD + dpart;
    const __half* __restrict__ V = g_Vh + (size_t)z * S_LEN * DHEAD + dpart;

    float k2[16] = {}, v2[16] = {};
    const int s0 = c * 128;

    #pragma unroll
    for (int it = 0; it < 2; it++) {
        const size_t base = (size_t)(s0 + it * 64 + squad) * DHEAD;
        float qf[16], kf[16], vf[16];
        ld16h(Q + base, qf);
        ld16h(K + base, kf);
        ld16h(V + base, vf);
        float dot = 0.f;
        #pragma unroll
        for (int j = 0; j < 16; j++) dot = fmaf(qf[j], kf[j], dot);
        dot += __shfl_xor_sync(0xFFFFFFFFu, dot, 1);
        dot += __shfl_xor_sync(0xFFFFFFFFu, dot, 2);
        const float w = 1.0f / (1.0f + expf(-dot));
        #pragma unroll
        for (int j = 0; j < 16; j++) {
            k2[j] = fmaf(w, kf[j], k2[j]);
            v2[j] = fmaf(w, vf[j], v2[j]);
        }
    }

    __shared__ __align__(16) float sk[64][64];
    __shared__ __align__(16) float sv[64][64];
    #pragma unroll
    for (int j = 0; j < 4; j++) {
        *(float4*)&sk[squad][dpart + j * 4] = *(float4*)&k2[j * 4];
        *(float4*)&sv[squad][dpart + j * 4] = *(float4*)&v2[j * 4];
    }
    __syncthreads();

    if (t < 128) {
        const int d = t & 63;
        float acc = 0.f;
        if (t < 64) {
            #pragma unroll 8
            for (int sq = 0; sq < 64; sq++) acc += sk[sq][d];
            g_k2p[(z * RCHUNK + c) * DHEAD + d] = acc;
        } else {
            #pragma unroll 8
            for (int sq = 0; sq < 64; sq++) acc += sv[sq][d];
            g_v2p[(z * RCHUNK + c) * DHEAD + d] = acc;
        }
    }
    __syncthreads();

    // Last block per z: combine partials; exact window scores; softmax.
    __shared__ int s_last;
    __shared__ __align__(16) float s_k2f[DHEAD];
    __shared__ __align__(16) float s_u[DMODEL];
    __shared__ __align__(16) float s_scr[NWIN];
    __shared__ float s_bconst;
    if (t == 0) {
        __threadfence();
        const int old = atomicAdd(&g_cnt[z], 1);
        s_last = ((old & (RCHUNK - 1)) == (RCHUNK - 1)) ? 1 : 0;
        if (s_last) __threadfence();
    }
    __syncthreads();
    if (!s_last) return;

    if (t < 128) {
        const int d = t & 63;
        float acc = 0.f;
        if (t < 64) {
            #pragma unroll
            for (int cc = 0; cc < RCHUNK; cc++)
                acc += g_k2p[(z * RCHUNK + cc) * DHEAD + d];
            g_k2[z * DHEAD + d] = acc;
            s_k2f[d] = acc;
        } else {
            #pragma unroll
            for (int cc = 0; cc < RCHUNK; cc++)
                acc += g_v2p[(z * RCHUNK + cc) * DHEAD + d];
            g_v2[z * DHEAD + d] = acc;
        }
    }
    __syncthreads();

    const int h = z & 7;
    const int b = z >> 3;

    // u[k] = sum_d Wq[64h+d, k] * k2[d]   (lanes coalesced over k)
    {
        float u0 = 0.f, u1 = 0.f;
        const float* __restrict__ Wqh = Wq + (size_t)(h * DHEAD) * DMODEL;
        #pragma unroll 8
        for (int d = 0; d < DHEAD; d++) {
            const float kv = s_k2f[d];
            u0 = fmaf(Wqh[(size_t)d * DMODEL + t],       kv, u0);
            u1 = fmaf(Wqh[(size_t)d * DMODEL + 256 + t], kv, u1);
        }
        s_u[t] = u0;
        s_u[256 + t] = u1;
    }
    if (t < 32) {
        float p = bq[h * DHEAD + t] * s_k2f[t]
                + bq[h * DHEAD + 32 + t] * s_k2f[32 + t];
        #pragma unroll
        for (int off = 16; off; off >>= 1)
            p += __shfl_xor_sync(0xFFFFFFFFu, p, off);
        if (t == 0) s_bconst = p;
    }
    __syncthreads();

    const float rscale = 1.0f / (8.0f * expf(beta[h]));

    {   // scores: w = t>>3 (0..31), part = t&7 handles 64 k-elements
        const int w = t >> 3, part = t & 7;
        const float4* __restrict__ xrow =
            (const float4*)(x + ((size_t)(64 * w + 63) * BSZ + b) * DMODEL) + part * 16;
        const float4* __restrict__ u4 = (const float4*)s_u + part * 16;
        float s = 0.f;
        #pragma unroll
        for (int j = 0; j < 16; j++) {
            const float4 xv = xrow[j];
            const float4 uv = u4[j];
            s = fmaf(xv.x, uv.x, s); s = fmaf(xv.y, uv.y, s);
            s = fmaf(xv.z, uv.z, s); s = fmaf(xv.w, uv.w, s);
        }
        s += __shfl_xor_sync(0xFFFFFFFFu, s, 1);
        s += __shfl_xor_sync(0xFFFFFFFFu, s, 2);
        s += __shfl_xor_sync(0xFFFFFFFFu, s, 4);
        if (part == 0) s_scr[w] = (s + s_bconst) * rscale;
    }
    __syncthreads();

    if (t < 32) {
        float s = s_scr[t];
        float mx = s;
        #pragma unroll
        for (int off = 16; off; off >>= 1)
            mx = fmaxf(mx, __shfl_xor_sync(0xFFFFFFFFu, mx, off));
        mx = fmaxf(mx, 0.f);
        const float e = expf(s - mx);
        float sum = e;
        #pragma unroll
        for (int off = 16; off; off >>= 1)
            sum += __shfl_xor_sync(0xFFFFFFFFu, sum, off);
        sum += expf(-mx);
        float cc = e / sum;
        if (t == 31) cc += 1.0f;
        g_c[z * NWIN + t] = cc;
    }
}

// ---------------------------------------------------------------------------
// Kernel D: coef_atomic — 256 blocks, block (z, nc) covers n = nc*32..+31.
// ILP layout: all 4 loads first, 4 partials, interleaved shuffle stages,
// then 4 atomics. Lane w scatters into out row 2016+w.
// ---------------------------------------------------------------------------
__global__ __launch_bounds__(256) void coef_atomic(
    const float* __restrict__ Wo, float* __restrict__ out)
{
    const int tid = threadIdx.x;
    const int z   = blockIdx.x >> 4;
    const int nc  = blockIdx.x & 15;
    const int h   = z & 7;
    const int batch = z >> 3;

    __shared__ __align__(16) float s_v2[DHEAD];
    __shared__ __align__(16) float s_c[NWIN];
    if (tid < DHEAD) s_v2[tid] = g_v2[z * DHEAD + tid];
    else if (tid < DHEAD + NWIN) s_c[tid - DHEAD] = g_c[z * NWIN + (tid - DHEAD)];
    __syncthreads();

    const int warp = tid >> 5;
    const int lane = tid & 31;
    const float2 v2l = *(const float2*)&s_v2[lane * 2];
    const float  cw  = s_c[lane];

    // 4 independent n-columns per warp; batch the loads for MLP.
    float2 wv[4];
    #pragma unroll
    for (int j = 0; j < 4; j++) {
        const int n = nc * 32 + warp * 4 + j;
        wv[j] = *(const float2*)(Wo + (size_t)n * DMODEL + h * DHEAD + lane * 2);
    }
    float dot[4];
    #pragma unroll
    for (int j = 0; j < 4; j++)
        dot[j] = v2l.x * wv[j].x + v2l.y * wv[j].y;
    #pragma unroll
    for (int off = 16; off; off >>= 1)
        #pragma unroll
        for (int j = 0; j < 4; j++)
            dot[j] += __shfl_xor_sync(0xFFFFFFFFu, dot[j], off);
    #pragma unroll
    for (int j = 0; j < 4; j++) {
        const int n = nc * 32 + warp * 4 + j;
        atomicAdd(&out[((size_t)((2016 + lane) * BSZ + batch)) * DMODEL + n],
                  cw * dot[j]);
    }
}

// ---------------------------------------------------------------------------
extern "C" void kernel_launch(void* const* d_in, const int* in_sizes, int n_in,
                              void* d_out, int out_size)
{
    const float* x    = (const float*)d_in[0];
    const float* Wq   = (const float*)d_in[1];
    const float* bq   = (const float*)d_in[2];
    const float* Wk   = (const float*)d_in[3];
    const float* bk   = (const float*)d_in[4];
    const float* Wv   = (const float*)d_in[5];
    const float* bv   = (const float*)d_in[6];
    const float* Wo   = (const float*)d_in[7];
    const float* bo   = (const float*)d_in[8];
    const float* beta = (const float*)d_in[9];
    float* out = (float*)d_out;

    cudaFuncSetAttribute(gemm_mma, cudaFuncAttributeMaxDynamicSharedMemorySize,
                         SMEM_BYTES);

    convert_xw<<<K1_BLOCKS, 256>>>(x, Wq, Wk, Wv, out, bo);
    gemm_mma<<<dim3(NTOT / 128, MROWS / 128), 256, SMEM_BYTES>>>(bq, bk, bv, beta);
    reduce_kv<<<dim3(ZB, RCHUNK), 256>>>(x, Wq, bq, beta);
    coef_atomic<<<256, 256>>>(Wo, out);
}